// round 12
// baseline (speedup 1.0000x reference)
#include <cuda_runtime.h>

// Problem constants
#define CC   64          // channels (CIN == COUT)
#define SS   128         // H == W
#define P    16384       // SS*SS pixels
#define NB   2           // batch

// ---------------- device scratch (static __device__, no allocations) ----------------
__device__ float  g_Q    [NB*CC*P];   // Q, later overwritten with t2 = r2*out2 - ft
__device__ float  g_Kc   [NB*CC*P];
__device__ float  g_Vc   [NB*CC*P];
__device__ float2 g_F    [NB*P];      // ortho fft2(out[:,32])
__device__ float2 g_bufA [NB*CC*P];   // FFT ping buffer
__device__ float  g_M    [CC*CC];
__device__ float  g_bias [CC];
__device__ float  g_part [2048];

// ---------------- warp FFT helper: AoS float2 row (stride 1) ----------------
__device__ __forceinline__ void fft128_row(float2* S, int lane, const float2* TW) {
    #pragma unroll
    for (int s = 1; s <= 7; s++) {
        int hf = 1 << (s - 1);
        __syncwarp();
        #pragma unroll
        for (int e = 0; e < 2; e++) {
            int bf = lane + 32*e;
            int j  = bf & (hf - 1);
            int i0 = ((bf >> (s - 1)) << s) + j;
            int i1 = i0 + hf;
            float2 w = TW[j << (7 - s)];
            float2 u = S[i0], v = S[i1];
            float tr = w.x*v.x - w.y*v.y;
            float ti = w.x*v.y + w.y*v.x;
            S[i0] = make_float2(u.x + tr, u.y + ti);
            S[i1] = make_float2(u.x - tr, u.y - ti);
        }
    }
    __syncwarp();
}

// ---------------- kernel: collapse conv chain to M, bias ----------------
__global__ void precompute_M(const float* __restrict__ w0,  const float* __restrict__ w0b,
                             const float* __restrict__ cv,  const float* __restrict__ cvb,
                             const float* __restrict__ cv1, const float* __restrict__ cv1b) {
    __shared__ float T[CC*CC];
    __shared__ float tb[CC];
    int tid = threadIdx.x;
    for (int idx = tid; idx < CC*CC; idx += 256) {
        int o = idx >> 6, c = idx & 63;
        float s = 0.f;
        #pragma unroll 8
        for (int k = 0; k < CC; k++) s += w0[o*CC + k] * cv[k*CC + c];
        T[idx] = s;
    }
    if (tid < CC) {
        float s = 0.f;
        for (int j = 0; j < CC; j++) s += w0[tid*CC + j] * cvb[j];
        tb[tid] = s + w0b[tid];
    }
    __syncthreads();
    for (int idx = tid; idx < CC*CC; idx += 256) {
        int o = idx >> 6, c = idx & 63;
        float s = 0.f;
        #pragma unroll 8
        for (int k = 0; k < CC; k++) s += cv1[o*CC + k] * T[k*CC + c];
        g_M[idx] = s;
    }
    if (tid < CC) {
        float s = 0.f;
        for (int k = 0; k < CC; k++) s += cv1[tid*CC + k] * tb[k];
        g_bias[tid] = s + cv1b[tid];
    }
}

// ---------------- kernel: Q/K/V 1x1 convs, one matrix per block (grid.z) ----------------
// grid (128 pixel-tiles, NB, 3), block 256, dyn smem 49152
__global__ void qkv_kernel(const float* __restrict__ fs,
                           const float* __restrict__ wq,
                           const float* __restrict__ wk,
                           const float* __restrict__ wv) {
    extern __shared__ float sm[];
    float* sw = sm;            // 64 * 64 (transposed: [k][o])
    float* sf = sm + 4096;     // 64 * 128
    int tid = threadIdx.x;
    int b   = blockIdx.y;
    int m   = blockIdx.z;
    int p0  = blockIdx.x * 128;

    const float* w = (m == 0) ? wq : ((m == 1) ? wk : wv);
    for (int idx = tid; idx < 4096; idx += 256) {
        int o = idx >> 6, k = idx & 63;
        sw[k*64 + o] = w[idx];
    }
    for (int idx = tid; idx < 8192; idx += 256) {
        int c = idx >> 7, pp = idx & 127;
        sf[c*128 + pp] = fs[((b*CC + c) << 14) + p0 + pp];
    }
    __syncthreads();

    int c0  = (tid >> 4) * 4;
    int pp0 = (tid & 15) * 8;

    float acc[4][8];
    #pragma unroll
    for (int i = 0; i < 4; i++)
        #pragma unroll
        for (int j = 0; j < 8; j++) acc[i][j] = 0.f;

    #pragma unroll 4
    for (int k = 0; k < 64; k++) {
        float4 w4 = *reinterpret_cast<const float4*>(&sw[k*64 + c0]);
        float4 fa = *reinterpret_cast<const float4*>(&sf[k*128 + pp0]);
        float4 fb = *reinterpret_cast<const float4*>(&sf[k*128 + pp0 + 4]);
        float wv4[4] = {w4.x, w4.y, w4.z, w4.w};
        float fv[8]  = {fa.x, fa.y, fa.z, fa.w, fb.x, fb.y, fb.z, fb.w};
        #pragma unroll
        for (int i = 0; i < 4; i++)
            #pragma unroll
            for (int j = 0; j < 8; j++)
                acc[i][j] += wv4[i] * fv[j];
    }
    float* dst = (m == 0) ? g_Q : ((m == 1) ? g_Kc : g_Vc);
    #pragma unroll
    for (int i = 0; i < 4; i++) {
        float* dp = dst + ((b*CC + c0 + i) << 14) + p0 + pp0;
        *reinterpret_cast<float4*>(dp)     = make_float4(acc[i][0], acc[i][1], acc[i][2], acc[i][3]);
        *reinterpret_cast<float4*>(dp + 4) = make_float4(acc[i][4], acc[i][5], acc[i][6], acc[i][7]);
    }
}

// ---------------- FUSED: attention + M@out GEMM + t2 epilogue + c32 row FFT ----------------
// grid (128 rows, NB), block 256, dyn smem 82432
__global__ void attn_pf_kernel(const float* __restrict__ relh,
                               const float* __restrict__ relw,
                               const float* __restrict__ ft,
                               const float* __restrict__ rate2) {
    extern __shared__ float sm[];
    float* sOut = sm;            // 64 * 128 = 8192
    float* sFt  = sm + 8192;     // 128 * 65 = 8320 (padded)
    float* sMT  = sm + 16512;    // 64 * 64  = 4096 (transposed [k][o])
    __shared__ float2 SF[128];   // c32 row FFT buffer
    __shared__ float2 TWF[64];   // forward twiddles
    int tid  = threadIdx.x;
    int wid  = tid >> 5;
    int lane = tid & 31;
    int h    = blockIdx.x;
    int b    = blockIdx.y;
    int p0   = h * 128;

    if (tid < 64) {
        float cs, sn;
        sincosf(-6.28318530717958647692f * (float)tid / 128.f, &cs, &sn);
        TWF[tid] = make_float2(cs, sn);
    }
    // prefetch ft and M into smem (independent of attention)
    for (int idx = tid; idx < 8192; idx += 256) {
        int pp = idx >> 6, c = idx & 63;
        sFt[pp*65 + c] = ft[((long)(b*P + p0 + pp))*64 + c];
    }
    for (int idx = tid; idx < 4096; idx += 256) {
        int o = idx >> 6, k = idx & 63;
        sMT[k*64 + o] = g_M[idx];
    }

    int c0  = (tid >> 4) * 4;     // 4 channels per thread
    int pp0 = (tid & 15) * 8;     // 8 pixels per thread

    #pragma unroll
    for (int i = 0; i < 4; i++) {
        int c = c0 + i;
        bool rowbias = (c < 32);
        float b0, b1, b2;
        if (rowbias) { b0 = relh[c*3+0]; b1 = relh[c*3+1]; b2 = relh[c*3+2]; }
        else         { int cc = c - 32; b0 = relw[cc*3+0]; b1 = relw[cc*3+1]; b2 = relw[cc*3+2]; }

        float Ks[3][10], Vs[3][10];
        const float* Kb = g_Kc + ((b*CC + c) << 14);
        const float* Vb = g_Vc + ((b*CC + c) << 14);
        #pragma unroll
        for (int dh = 0; dh < 3; dh++) {
            int h2 = h - 1 + dh;
            if ((unsigned)h2 < 128u) {
                const float* kr = Kb + h2*128;
                const float* vr = Vb + h2*128;
                float4 ka = *reinterpret_cast<const float4*>(kr + pp0);
                float4 kc = *reinterpret_cast<const float4*>(kr + pp0 + 4);
                float4 va = *reinterpret_cast<const float4*>(vr + pp0);
                float4 vc = *reinterpret_cast<const float4*>(vr + pp0 + 4);
                Ks[dh][1]=ka.x; Ks[dh][2]=ka.y; Ks[dh][3]=ka.z; Ks[dh][4]=ka.w;
                Ks[dh][5]=kc.x; Ks[dh][6]=kc.y; Ks[dh][7]=kc.z; Ks[dh][8]=kc.w;
                Vs[dh][1]=va.x; Vs[dh][2]=va.y; Vs[dh][3]=va.z; Vs[dh][4]=va.w;
                Vs[dh][5]=vc.x; Vs[dh][6]=vc.y; Vs[dh][7]=vc.z; Vs[dh][8]=vc.w;
                Ks[dh][0] = (pp0 > 0)   ? kr[pp0-1] : 0.f;
                Ks[dh][9] = (pp0 < 120) ? kr[pp0+8] : 0.f;
                Vs[dh][0] = (pp0 > 0)   ? vr[pp0-1] : 0.f;
                Vs[dh][9] = (pp0 < 120) ? vr[pp0+8] : 0.f;
            } else {
                #pragma unroll
                for (int m2 = 0; m2 < 10; m2++) { Ks[dh][m2] = 0.f; Vs[dh][m2] = 0.f; }
            }
        }
        const float* qp = g_Q + ((b*CC + c) << 14) + p0 + pp0;
        float4 qa = *reinterpret_cast<const float4*>(qp);
        float4 qb = *reinterpret_cast<const float4*>(qp + 4);
        float q[8] = {qa.x, qa.y, qa.z, qa.w, qb.x, qb.y, qb.z, qb.w};

        float outv[8];
        #pragma unroll
        for (int j = 0; j < 8; j++) {
            float l[9], vv[9];
            float mx = -1e30f;
            #pragma unroll
            for (int dh = 0; dh < 3; dh++) {
                float bh = (dh == 0) ? b0 : ((dh == 1) ? b1 : b2);
                #pragma unroll
                for (int dw = 0; dw < 3; dw++) {
                    float bias = rowbias ? bh : ((dw == 0) ? b0 : ((dw == 1) ? b1 : b2));
                    int t = dh*3 + dw;
                    l[t]  = q[j] * (Ks[dh][j + dw] + bias);
                    vv[t] = Vs[dh][j + dw];
                    mx = fmaxf(mx, l[t]);
                }
            }
            float se = 0.f, acc = 0.f;
            #pragma unroll
            for (int t = 0; t < 9; t++) {
                float e = __expf(l[t] - mx);
                se  += e;
                acc += e * vv[t];
            }
            outv[j] = acc / se;
        }
        *reinterpret_cast<float4*>(&sOut[c*128 + pp0])     = make_float4(outv[0], outv[1], outv[2], outv[3]);
        *reinterpret_cast<float4*>(&sOut[c*128 + pp0 + 4]) = make_float4(outv[4], outv[5], outv[6], outv[7]);
    }
    __syncthreads();

    // ---- phase 2: GEMM out2 = M@out + bias; t2 = r2*out2 - ft ----
    float acc[4][8];
    #pragma unroll
    for (int i = 0; i < 4; i++) {
        float bb = g_bias[c0 + i];
        #pragma unroll
        for (int j = 0; j < 8; j++) acc[i][j] = bb;
    }
    #pragma unroll 4
    for (int k = 0; k < 64; k++) {
        float4 m4 = *reinterpret_cast<const float4*>(&sMT[k*64 + c0]);
        float4 fa = *reinterpret_cast<const float4*>(&sOut[k*128 + pp0]);
        float4 fb = *reinterpret_cast<const float4*>(&sOut[k*128 + pp0 + 4]);
        float mv[4] = {m4.x, m4.y, m4.z, m4.w};
        float fv[8] = {fa.x, fa.y, fa.z, fa.w, fb.x, fb.y, fb.z, fb.w};
        #pragma unroll
        for (int i = 0; i < 4; i++)
            #pragma unroll
            for (int j = 0; j < 8; j++)
                acc[i][j] += mv[i] * fv[j];
    }

    float r2 = rate2[0];
    #pragma unroll
    for (int i = 0; i < 4; i++) {
        int c = c0 + i;
        float o8[8];
        #pragma unroll
        for (int j = 0; j < 8; j++)
            o8[j] = r2 * acc[i][j] - sFt[(pp0 + j)*65 + c];
        float* dp = g_Q + ((b*CC + c) << 14) + p0 + pp0;
        *reinterpret_cast<float4*>(dp)     = make_float4(o8[0], o8[1], o8[2], o8[3]);
        *reinterpret_cast<float4*>(dp + 4) = make_float4(o8[4], o8[5], o8[6], o8[7]);
    }

    // ---- phase 3 (warp 0 only): forward row FFT of channel-32 row h -> g_bufA ----
    if (wid == 0) {
        #pragma unroll
        for (int e = 0; e < 4; e++) {
            int j = lane + e*32;
            int r = __brev((unsigned)j) >> 25;
            SF[r] = make_float2(sOut[32*128 + j], 0.f);
        }
        fft128_row(SF, lane, TWF);
        #pragma unroll
        for (int e = 0; e < 4; e++) {
            int j = lane + e*32;
            g_bufA[(long)b*P + j*128 + h] = SF[j];   // transposed store
        }
    }
}

// ---------------- forward column FFT (2 transforms) -> g_F ----------------
// grid 32 (= 2 transforms * 16 row-blocks), block 256
__global__ void fwd_pass2() {
    __shared__ float2 S[8][128];
    __shared__ float2 TW[64];
    int tid  = threadIdx.x;
    int t    = blockIdx.x >> 4;
    int rb   = blockIdx.x & 15;
    int wid  = tid >> 5;
    int lane = tid & 31;
    int a    = rb*8 + wid;

    if (tid < 64) {
        float cs, sn;
        sincosf(-6.28318530717958647692f * (float)tid / 128.f, &cs, &sn);
        TW[tid] = make_float2(cs, sn);
    }
    __syncthreads();

    const float2* p = g_bufA + (long)t*P + a*128;
    #pragma unroll
    for (int e = 0; e < 4; e++) {
        int j = lane + e*32;
        int r = __brev((unsigned)j) >> 25;
        S[wid][r] = p[j];
    }
    fft128_row(S[wid], lane, TW);
    __syncthreads();

    const float sc = 1.f/128.f;   // ortho fft2
    #pragma unroll
    for (int it = 0; it < 4; it++) {
        int el = it*256 + tid;
        int j  = el >> 3, aa = el & 7;
        float2 v = S[aa][j];
        g_F[(long)t*P + j*128 + rb*8 + aa] = make_float2(v.x*sc, v.y*sc);
    }
}

// ---------------- FUSED: weights1 i-sum (512MB stream) + freq-mul + row iFFT --------
// grid 1024 (= 64 channels * 16 u-blocks), block 256
__global__ void __launch_bounds__(256) invA_kernel(const float* __restrict__ w1r,
                                                   const float* __restrict__ w1i) {
    __shared__ float  sR[1024], sI[1024];
    __shared__ float2 S[8][128];
    __shared__ float2 TW[64];
    int tid  = threadIdx.x;
    int c    = blockIdx.x >> 4;
    int rb   = blockIdx.x & 15;
    int wid  = tid >> 5;
    int lane = tid & 31;

    if (tid < 64) {
        float cs, sn;
        sincosf(6.28318530717958647692f * (float)tid / 128.f, &cs, &sn);
        TW[tid] = make_float2(cs, sn);
    }

    // ---- phase A: sum over i=0..63; thread owns one float4 of the block's
    //      1024-point uv chunk. i stride = P floats = 4096 float4.
    const float4* pR = reinterpret_cast<const float4*>(w1r + (size_t)c*CC*P + rb*1024) + tid;
    const float4* pI = reinterpret_cast<const float4*>(w1i + (size_t)c*CC*P + rb*1024) + tid;

    float4 aR = make_float4(0,0,0,0), aI = make_float4(0,0,0,0);
    #pragma unroll
    for (int g = 0; g < 8; g++) {
        float4 R[8], I[8];
        #pragma unroll
        for (int j = 0; j < 8; j++) R[j] = __ldcs(&pR[(g*8 + j)*4096]);
        #pragma unroll
        for (int j = 0; j < 8; j++) I[j] = __ldcs(&pI[(g*8 + j)*4096]);
        #pragma unroll
        for (int j = 0; j < 8; j++) {
            aR.x += R[j].x; aR.y += R[j].y; aR.z += R[j].z; aR.w += R[j].w;
            aI.x += I[j].x; aI.y += I[j].y; aI.z += I[j].z; aI.w += I[j].w;
        }
    }
    reinterpret_cast<float4*>(sR)[tid] = aR;
    reinterpret_cast<float4*>(sI)[tid] = aI;
    __syncthreads();

    // ---- phase B: per batch image: multiply by F, row FFT, transposed store ----
    #pragma unroll
    for (int b = 0; b < NB; b++) {
        const float2* Fp = g_F + b*P + (rb*8 + wid)*128;
        #pragma unroll
        for (int e = 0; e < 4; e++) {
            int j = lane + e*32;
            int r = __brev((unsigned)j) >> 25;
            float2 F  = Fp[j];
            float  sr = sR[wid*128 + j];
            float  si = sI[wid*128 + j];
            S[wid][r] = make_float2(sr*F.x - si*F.y, sr*F.y + si*F.x);
        }
        fft128_row(S[wid], lane, TW);
        __syncthreads();

        long t = (long)b*64 + c;
        #pragma unroll
        for (int it = 0; it < 4; it++) {
            int el = it*256 + tid;
            int j  = el >> 3, aa = el & 7;
            g_bufA[t*P + j*128 + rb*8 + aa] = S[aa][j];   // transposed
        }
        __syncthreads();
    }
}

// ---------------- inverse pass 2 + fused loss ----------------
// grid 2048, block 256
__global__ void inv_pass2_loss(const float* __restrict__ rate1) {
    __shared__ float2 S[8][128];
    __shared__ float2 TW[64];
    __shared__ float red[256];
    int tid  = threadIdx.x;
    int t    = blockIdx.x >> 4;
    int rb   = blockIdx.x & 15;
    int wid  = tid >> 5;
    int lane = tid & 31;
    int a    = rb*8 + wid;          // v row

    if (tid < 64) {
        float cs, sn;
        sincosf(6.28318530717958647692f * (float)tid / 128.f, &cs, &sn);
        TW[tid] = make_float2(cs, sn);
    }
    __syncthreads();

    const float2* p = g_bufA + (long)t*P + a*128;
    #pragma unroll
    for (int e = 0; e < 4; e++) {
        int j = lane + e*32;
        int r = __brev((unsigned)j) >> 25;
        S[wid][r] = p[j];
    }
    fft128_row(S[wid], lane, TW);
    __syncthreads();

    // loss: (r1/128 * Re + t2)^2 over this block's 1024 output elements
    float r1s = rate1[0] * (1.f/128.f);
    const float* t2 = g_Q + (long)t*P;
    float local = 0.f;
    #pragma unroll
    for (int it = 0; it < 4; it++) {
        int el = it*256 + tid;
        int j  = el >> 3, aa = el & 7;
        float val = r1s * S[aa][j].x + t2[j*128 + rb*8 + aa];
        local += val * val;
    }
    red[tid] = local;
    __syncthreads();
    for (int s = 128; s > 0; s >>= 1) {
        if (tid < s) red[tid] += red[tid + s];
        __syncthreads();
    }
    if (tid == 0) g_part[blockIdx.x] = red[0];
}

__global__ void reduce_kernel(float* __restrict__ out) {
    __shared__ float s[256];
    float v = 0.f;
    #pragma unroll
    for (int k = 0; k < 8; k++) v += g_part[threadIdx.x + k*256];
    s[threadIdx.x] = v;
    __syncthreads();
    for (int st = 128; st > 0; st >>= 1) {
        if (threadIdx.x < st) s[threadIdx.x] += s[threadIdx.x + st];
        __syncthreads();
    }
    if (threadIdx.x == 0) out[0] = s[0] / 2097152.0f;  // mean over 2*64*128*128
}

// ---------------- host ----------------
extern "C" void kernel_launch(void* const* d_in, const int* in_sizes, int n_in,
                              void* d_out, int out_size) {
    const float* fs    = (const float*)d_in[0];
    const float* ft    = (const float*)d_in[1];
    const float* w_q   = (const float*)d_in[2];
    const float* w_k   = (const float*)d_in[3];
    const float* w_v   = (const float*)d_in[4];
    const float* rel_h = (const float*)d_in[5];
    const float* rel_w = (const float*)d_in[6];
    const float* w1r   = (const float*)d_in[7];
    const float* w1i   = (const float*)d_in[8];
    const float* w0w   = (const float*)d_in[9];
    const float* w0b   = (const float*)d_in[10];
    const float* cvw   = (const float*)d_in[11];
    const float* cvb   = (const float*)d_in[12];
    const float* cv1w  = (const float*)d_in[13];
    const float* cv1b  = (const float*)d_in[14];
    const float* rate1 = (const float*)d_in[15];
    const float* rate2 = (const float*)d_in[16];

    static bool s_init = false;
    if (!s_init) {
        cudaFuncSetAttribute(qkv_kernel,     cudaFuncAttributeMaxDynamicSharedMemorySize, 49152);
        cudaFuncSetAttribute(attn_pf_kernel, cudaFuncAttributeMaxDynamicSharedMemorySize, 82432);
        s_init = true;
    }

    precompute_M<<<1, 256>>>(w0w, w0b, cvw, cvb, cv1w, cv1b);              // 1
    qkv_kernel<<<dim3(128, 2, 3), 256, 49152>>>(fs, w_q, w_k, w_v);        // 2
    attn_pf_kernel<<<dim3(128, 2), 256, 82432>>>(rel_h, rel_w, ft, rate2); // 3 (+c32 row FFT)
    fwd_pass2<<<32, 256>>>();                                              // 4
    invA_kernel<<<1024, 256>>>(w1r, w1i);                                  // 5 (512MB stream)
    inv_pass2_loss<<<2048, 256>>>(rate1);                                  // 6
    reduce_kernel<<<1, 256>>>((float*)d_out);                              // 7
}

// round 13
// speedup vs baseline: 1.1834x; 1.1834x over previous
#include <cuda_runtime.h>

// Problem constants
#define CC   64          // channels (CIN == COUT)
#define SS   128         // H == W
#define P    16384       // SS*SS pixels
#define NB   2           // batch

// ---------------- device scratch (static __device__, no allocations) ----------------
__device__ float  g_Q    [NB*CC*P];   // Q, later overwritten with t2 = r2*out2 - ft
__device__ float  g_Kc   [NB*CC*P];
__device__ float  g_Vc   [NB*CC*P];
__device__ float2 g_F    [NB*P];      // ortho fft2(out[:,32])
__device__ float2 g_bufA [NB*CC*P];   // FFT ping buffer
__device__ float  g_wsumR[CC*P];
__device__ float  g_wsumI[CC*P];
__device__ float  g_M    [CC*CC];
__device__ float  g_bias [CC];
__device__ float  g_part [2048];

// ---------------- warp FFT helper: AoS float2 row (stride 1) ----------------
__device__ __forceinline__ void fft128_row(float2* S, int lane, const float2* TW) {
    #pragma unroll
    for (int s = 1; s <= 7; s++) {
        int hf = 1 << (s - 1);
        __syncwarp();
        #pragma unroll
        for (int e = 0; e < 2; e++) {
            int bf = lane + 32*e;
            int j  = bf & (hf - 1);
            int i0 = ((bf >> (s - 1)) << s) + j;
            int i1 = i0 + hf;
            float2 w = TW[j << (7 - s)];
            float2 u = S[i0], v = S[i1];
            float tr = w.x*v.x - w.y*v.y;
            float ti = w.x*v.y + w.y*v.x;
            S[i0] = make_float2(u.x + tr, u.y + ti);
            S[i1] = make_float2(u.x - tr, u.y - ti);
        }
    }
    __syncwarp();
}

// ---------------- kernel: collapse conv chain to M, bias ----------------
__global__ void precompute_M(const float* __restrict__ w0,  const float* __restrict__ w0b,
                             const float* __restrict__ cv,  const float* __restrict__ cvb,
                             const float* __restrict__ cv1, const float* __restrict__ cv1b) {
    __shared__ float T[CC*CC];
    __shared__ float tb[CC];
    int tid = threadIdx.x;
    for (int idx = tid; idx < CC*CC; idx += 256) {
        int o = idx >> 6, c = idx & 63;
        float s = 0.f;
        #pragma unroll 8
        for (int k = 0; k < CC; k++) s += w0[o*CC + k] * cv[k*CC + c];
        T[idx] = s;
    }
    if (tid < CC) {
        float s = 0.f;
        for (int j = 0; j < CC; j++) s += w0[tid*CC + j] * cvb[j];
        tb[tid] = s + w0b[tid];
    }
    __syncthreads();
    for (int idx = tid; idx < CC*CC; idx += 256) {
        int o = idx >> 6, c = idx & 63;
        float s = 0.f;
        #pragma unroll 8
        for (int k = 0; k < CC; k++) s += cv1[o*CC + k] * T[k*CC + c];
        g_M[idx] = s;
    }
    if (tid < CC) {
        float s = 0.f;
        for (int k = 0; k < CC; k++) s += cv1[tid*CC + k] * tb[k];
        g_bias[tid] = s + cv1b[tid];
    }
}

// ---------------- kernel: Q/K/V 1x1 convs, one matrix per block (grid.z) ----------------
// grid (128 pixel-tiles, NB, 3), block 256, dyn smem 49152
__global__ void qkv_kernel(const float* __restrict__ fs,
                           const float* __restrict__ wq,
                           const float* __restrict__ wk,
                           const float* __restrict__ wv) {
    extern __shared__ float sm[];
    float* sw = sm;            // 64 * 64 (transposed: [k][o])
    float* sf = sm + 4096;     // 64 * 128
    int tid = threadIdx.x;
    int b   = blockIdx.y;
    int m   = blockIdx.z;
    int p0  = blockIdx.x * 128;

    const float* w = (m == 0) ? wq : ((m == 1) ? wk : wv);
    for (int idx = tid; idx < 4096; idx += 256) {
        int o = idx >> 6, k = idx & 63;
        sw[k*64 + o] = w[idx];
    }
    for (int idx = tid; idx < 8192; idx += 256) {
        int c = idx >> 7, pp = idx & 127;
        sf[c*128 + pp] = fs[((b*CC + c) << 14) + p0 + pp];
    }
    __syncthreads();

    int c0  = (tid >> 4) * 4;
    int pp0 = (tid & 15) * 8;

    float acc[4][8];
    #pragma unroll
    for (int i = 0; i < 4; i++)
        #pragma unroll
        for (int j = 0; j < 8; j++) acc[i][j] = 0.f;

    #pragma unroll 4
    for (int k = 0; k < 64; k++) {
        float4 w4 = *reinterpret_cast<const float4*>(&sw[k*64 + c0]);
        float4 fa = *reinterpret_cast<const float4*>(&sf[k*128 + pp0]);
        float4 fb = *reinterpret_cast<const float4*>(&sf[k*128 + pp0 + 4]);
        float wv4[4] = {w4.x, w4.y, w4.z, w4.w};
        float fv[8]  = {fa.x, fa.y, fa.z, fa.w, fb.x, fb.y, fb.z, fb.w};
        #pragma unroll
        for (int i = 0; i < 4; i++)
            #pragma unroll
            for (int j = 0; j < 8; j++)
                acc[i][j] += wv4[i] * fv[j];
    }
    float* dst = (m == 0) ? g_Q : ((m == 1) ? g_Kc : g_Vc);
    #pragma unroll
    for (int i = 0; i < 4; i++) {
        float* dp = dst + ((b*CC + c0 + i) << 14) + p0 + pp0;
        *reinterpret_cast<float4*>(dp)     = make_float4(acc[i][0], acc[i][1], acc[i][2], acc[i][3]);
        *reinterpret_cast<float4*>(dp + 4) = make_float4(acc[i][4], acc[i][5], acc[i][6], acc[i][7]);
    }
}

// ---------------- FUSED: attention + M@out GEMM + t2 epilogue + c32 row FFT ----------------
// grid (128 rows, NB), block 256, dyn smem 82432
__global__ void attn_pf_kernel(const float* __restrict__ relh,
                               const float* __restrict__ relw,
                               const float* __restrict__ ft,
                               const float* __restrict__ rate2) {
    extern __shared__ float sm[];
    float* sOut = sm;            // 64 * 128 = 8192
    float* sFt  = sm + 8192;     // 128 * 65 = 8320 (padded)
    float* sMT  = sm + 16512;    // 64 * 64  = 4096 (transposed [k][o])
    __shared__ float2 SF[128];   // c32 row FFT buffer
    __shared__ float2 TWF[64];   // forward twiddles
    int tid  = threadIdx.x;
    int wid  = tid >> 5;
    int lane = tid & 31;
    int h    = blockIdx.x;
    int b    = blockIdx.y;
    int p0   = h * 128;

    if (tid < 64) {
        float cs, sn;
        sincosf(-6.28318530717958647692f * (float)tid / 128.f, &cs, &sn);
        TWF[tid] = make_float2(cs, sn);
    }
    // prefetch ft and M into smem (independent of attention)
    for (int idx = tid; idx < 8192; idx += 256) {
        int pp = idx >> 6, c = idx & 63;
        sFt[pp*65 + c] = ft[((long)(b*P + p0 + pp))*64 + c];
    }
    for (int idx = tid; idx < 4096; idx += 256) {
        int o = idx >> 6, k = idx & 63;
        sMT[k*64 + o] = g_M[idx];
    }

    int c0  = (tid >> 4) * 4;     // 4 channels per thread
    int pp0 = (tid & 15) * 8;     // 8 pixels per thread

    #pragma unroll
    for (int i = 0; i < 4; i++) {
        int c = c0 + i;
        bool rowbias = (c < 32);
        float b0, b1, b2;
        if (rowbias) { b0 = relh[c*3+0]; b1 = relh[c*3+1]; b2 = relh[c*3+2]; }
        else         { int cc = c - 32; b0 = relw[cc*3+0]; b1 = relw[cc*3+1]; b2 = relw[cc*3+2]; }

        float Ks[3][10], Vs[3][10];
        const float* Kb = g_Kc + ((b*CC + c) << 14);
        const float* Vb = g_Vc + ((b*CC + c) << 14);
        #pragma unroll
        for (int dh = 0; dh < 3; dh++) {
            int h2 = h - 1 + dh;
            if ((unsigned)h2 < 128u) {
                const float* kr = Kb + h2*128;
                const float* vr = Vb + h2*128;
                float4 ka = *reinterpret_cast<const float4*>(kr + pp0);
                float4 kc = *reinterpret_cast<const float4*>(kr + pp0 + 4);
                float4 va = *reinterpret_cast<const float4*>(vr + pp0);
                float4 vc = *reinterpret_cast<const float4*>(vr + pp0 + 4);
                Ks[dh][1]=ka.x; Ks[dh][2]=ka.y; Ks[dh][3]=ka.z; Ks[dh][4]=ka.w;
                Ks[dh][5]=kc.x; Ks[dh][6]=kc.y; Ks[dh][7]=kc.z; Ks[dh][8]=kc.w;
                Vs[dh][1]=va.x; Vs[dh][2]=va.y; Vs[dh][3]=va.z; Vs[dh][4]=va.w;
                Vs[dh][5]=vc.x; Vs[dh][6]=vc.y; Vs[dh][7]=vc.z; Vs[dh][8]=vc.w;
                Ks[dh][0] = (pp0 > 0)   ? kr[pp0-1] : 0.f;
                Ks[dh][9] = (pp0 < 120) ? kr[pp0+8] : 0.f;
                Vs[dh][0] = (pp0 > 0)   ? vr[pp0-1] : 0.f;
                Vs[dh][9] = (pp0 < 120) ? vr[pp0+8] : 0.f;
            } else {
                #pragma unroll
                for (int m2 = 0; m2 < 10; m2++) { Ks[dh][m2] = 0.f; Vs[dh][m2] = 0.f; }
            }
        }
        const float* qp = g_Q + ((b*CC + c) << 14) + p0 + pp0;
        float4 qa = *reinterpret_cast<const float4*>(qp);
        float4 qb = *reinterpret_cast<const float4*>(qp + 4);
        float q[8] = {qa.x, qa.y, qa.z, qa.w, qb.x, qb.y, qb.z, qb.w};

        float outv[8];
        #pragma unroll
        for (int j = 0; j < 8; j++) {
            float l[9], vv[9];
            float mx = -1e30f;
            #pragma unroll
            for (int dh = 0; dh < 3; dh++) {
                float bh = (dh == 0) ? b0 : ((dh == 1) ? b1 : b2);
                #pragma unroll
                for (int dw = 0; dw < 3; dw++) {
                    float bias = rowbias ? bh : ((dw == 0) ? b0 : ((dw == 1) ? b1 : b2));
                    int t = dh*3 + dw;
                    l[t]  = q[j] * (Ks[dh][j + dw] + bias);
                    vv[t] = Vs[dh][j + dw];
                    mx = fmaxf(mx, l[t]);
                }
            }
            float se = 0.f, acc = 0.f;
            #pragma unroll
            for (int t = 0; t < 9; t++) {
                float e = __expf(l[t] - mx);
                se  += e;
                acc += e * vv[t];
            }
            outv[j] = acc / se;
        }
        *reinterpret_cast<float4*>(&sOut[c*128 + pp0])     = make_float4(outv[0], outv[1], outv[2], outv[3]);
        *reinterpret_cast<float4*>(&sOut[c*128 + pp0 + 4]) = make_float4(outv[4], outv[5], outv[6], outv[7]);
    }
    __syncthreads();

    // ---- phase 2: GEMM out2 = M@out + bias; t2 = r2*out2 - ft ----
    float acc[4][8];
    #pragma unroll
    for (int i = 0; i < 4; i++) {
        float bb = g_bias[c0 + i];
        #pragma unroll
        for (int j = 0; j < 8; j++) acc[i][j] = bb;
    }
    #pragma unroll 4
    for (int k = 0; k < 64; k++) {
        float4 m4 = *reinterpret_cast<const float4*>(&sMT[k*64 + c0]);
        float4 fa = *reinterpret_cast<const float4*>(&sOut[k*128 + pp0]);
        float4 fb = *reinterpret_cast<const float4*>(&sOut[k*128 + pp0 + 4]);
        float mv[4] = {m4.x, m4.y, m4.z, m4.w};
        float fv[8] = {fa.x, fa.y, fa.z, fa.w, fb.x, fb.y, fb.z, fb.w};
        #pragma unroll
        for (int i = 0; i < 4; i++)
            #pragma unroll
            for (int j = 0; j < 8; j++)
                acc[i][j] += mv[i] * fv[j];
    }

    float r2 = rate2[0];
    #pragma unroll
    for (int i = 0; i < 4; i++) {
        int c = c0 + i;
        float o8[8];
        #pragma unroll
        for (int j = 0; j < 8; j++)
            o8[j] = r2 * acc[i][j] - sFt[(pp0 + j)*65 + c];
        float* dp = g_Q + ((b*CC + c) << 14) + p0 + pp0;
        *reinterpret_cast<float4*>(dp)     = make_float4(o8[0], o8[1], o8[2], o8[3]);
        *reinterpret_cast<float4*>(dp + 4) = make_float4(o8[4], o8[5], o8[6], o8[7]);
    }

    // ---- phase 3 (warp 0 only): forward row FFT of channel-32 row h -> g_bufA ----
    if (wid == 0) {
        #pragma unroll
        for (int e = 0; e < 4; e++) {
            int j = lane + e*32;
            int r = __brev((unsigned)j) >> 25;
            SF[r] = make_float2(sOut[32*128 + j], 0.f);
        }
        fft128_row(SF, lane, TWF);
        #pragma unroll
        for (int e = 0; e < 4; e++) {
            int j = lane + e*32;
            g_bufA[(long)b*P + j*128 + h] = SF[j];   // transposed store
        }
    }
}

// ---------------- forward column FFT (2 transforms) -> g_F ----------------
// grid 32 (= 2 transforms * 16 row-blocks), block 256
__global__ void fwd_pass2() {
    __shared__ float2 S[8][128];
    __shared__ float2 TW[64];
    int tid  = threadIdx.x;
    int t    = blockIdx.x >> 4;
    int rb   = blockIdx.x & 15;
    int wid  = tid >> 5;
    int lane = tid & 31;
    int a    = rb*8 + wid;

    if (tid < 64) {
        float cs, sn;
        sincosf(-6.28318530717958647692f * (float)tid / 128.f, &cs, &sn);
        TW[tid] = make_float2(cs, sn);
    }
    __syncthreads();

    const float2* p = g_bufA + (long)t*P + a*128;
    #pragma unroll
    for (int e = 0; e < 4; e++) {
        int j = lane + e*32;
        int r = __brev((unsigned)j) >> 25;
        S[wid][r] = p[j];
    }
    fft128_row(S[wid], lane, TW);
    __syncthreads();

    const float sc = 1.f/128.f;   // ortho fft2
    #pragma unroll
    for (int it = 0; it < 4; it++) {
        int el = it*256 + tid;
        int j  = el >> 3, aa = el & 7;
        float2 v = S[aa][j];
        g_F[(long)t*P + j*128 + rb*8 + aa] = make_float2(v.x*sc, v.y*sc);
    }
}

// ---------------- wsum chunk: 16 channels of the 512MB weights stream ----------------
// grid (32 rb, 16 ch), block 128; c = c0 + blockIdx.y
__global__ void __launch_bounds__(128) wsum_kernel(const float* __restrict__ w1r,
                                                   const float* __restrict__ w1i,
                                                   int c0) {
    int tid = threadIdx.x;
    int c   = c0 + blockIdx.y;
    int f4  = blockIdx.x * 128 + tid;   // float4 index in [0,4096)

    const float4* pR = reinterpret_cast<const float4*>(w1r + (size_t)c*CC*P) + f4;
    const float4* pI = reinterpret_cast<const float4*>(w1i + (size_t)c*CC*P) + f4;

    float4 aR = make_float4(0,0,0,0), aI = make_float4(0,0,0,0);
    #pragma unroll
    for (int g = 0; g < 8; g++) {
        float4 R[8], I[8];
        #pragma unroll
        for (int j = 0; j < 8; j++) R[j] = __ldcs(&pR[(g*8 + j)*4096]);
        #pragma unroll
        for (int j = 0; j < 8; j++) I[j] = __ldcs(&pI[(g*8 + j)*4096]);
        #pragma unroll
        for (int j = 0; j < 8; j++) {
            aR.x += R[j].x; aR.y += R[j].y; aR.z += R[j].z; aR.w += R[j].w;
            aI.x += I[j].x; aI.y += I[j].y; aI.z += I[j].z; aI.w += I[j].w;
        }
    }
    reinterpret_cast<float4*>(g_wsumR)[c*4096 + f4] = aR;
    reinterpret_cast<float4*>(g_wsumI)[c*4096 + f4] = aI;
}

// ---------------- invB: freq-mul (wsum x F) + row iFFT -> g_bufA ----------------
// grid 1024 (= 64 channels * 16 u-blocks), block 256
__global__ void __launch_bounds__(256) invB_kernel() {
    __shared__ float2 S[8][128];
    __shared__ float2 TW[64];
    int tid  = threadIdx.x;
    int c    = blockIdx.x >> 4;
    int rb   = blockIdx.x & 15;
    int wid  = tid >> 5;
    int lane = tid & 31;

    if (tid < 64) {
        float cs, sn;
        sincosf(6.28318530717958647692f * (float)tid / 128.f, &cs, &sn);
        TW[tid] = make_float2(cs, sn);
    }
    __syncthreads();

    const float* wr = g_wsumR + c*P + (rb*8 + wid)*128;
    const float* wi = g_wsumI + c*P + (rb*8 + wid)*128;
    float srv[4], siv[4];
    #pragma unroll
    for (int e = 0; e < 4; e++) {
        int j = lane + e*32;
        srv[e] = wr[j];
        siv[e] = wi[j];
    }

    #pragma unroll
    for (int b = 0; b < NB; b++) {
        const float2* Fp = g_F + b*P + (rb*8 + wid)*128;
        #pragma unroll
        for (int e = 0; e < 4; e++) {
            int j = lane + e*32;
            int r = __brev((unsigned)j) >> 25;
            float2 F = Fp[j];
            S[wid][r] = make_float2(srv[e]*F.x - siv[e]*F.y, srv[e]*F.y + siv[e]*F.x);
        }
        fft128_row(S[wid], lane, TW);
        __syncthreads();

        long t = (long)b*64 + c;
        #pragma unroll
        for (int it = 0; it < 4; it++) {
            int el = it*256 + tid;
            int j  = el >> 3, aa = el & 7;
            g_bufA[t*P + j*128 + rb*8 + aa] = S[aa][j];   // transposed
        }
        __syncthreads();
    }
}

// ---------------- inverse pass 2 + fused loss ----------------
// grid 2048, block 256
__global__ void inv_pass2_loss(const float* __restrict__ rate1) {
    __shared__ float2 S[8][128];
    __shared__ float2 TW[64];
    __shared__ float red[256];
    int tid  = threadIdx.x;
    int t    = blockIdx.x >> 4;
    int rb   = blockIdx.x & 15;
    int wid  = tid >> 5;
    int lane = tid & 31;
    int a    = rb*8 + wid;          // v row

    if (tid < 64) {
        float cs, sn;
        sincosf(6.28318530717958647692f * (float)tid / 128.f, &cs, &sn);
        TW[tid] = make_float2(cs, sn);
    }
    __syncthreads();

    const float2* p = g_bufA + (long)t*P + a*128;
    #pragma unroll
    for (int e = 0; e < 4; e++) {
        int j = lane + e*32;
        int r = __brev((unsigned)j) >> 25;
        S[wid][r] = p[j];
    }
    fft128_row(S[wid], lane, TW);
    __syncthreads();

    // loss: (r1/128 * Re + t2)^2 over this block's 1024 output elements
    float r1s = rate1[0] * (1.f/128.f);
    const float* t2 = g_Q + (long)t*P;
    float local = 0.f;
    #pragma unroll
    for (int it = 0; it < 4; it++) {
        int el = it*256 + tid;
        int j  = el >> 3, aa = el & 7;
        float val = r1s * S[aa][j].x + t2[j*128 + rb*8 + aa];
        local += val * val;
    }
    red[tid] = local;
    __syncthreads();
    for (int s = 128; s > 0; s >>= 1) {
        if (tid < s) red[tid] += red[tid + s];
        __syncthreads();
    }
    if (tid == 0) g_part[blockIdx.x] = red[0];
}

__global__ void reduce_kernel(float* __restrict__ out) {
    __shared__ float s[256];
    float v = 0.f;
    #pragma unroll
    for (int k = 0; k < 8; k++) v += g_part[threadIdx.x + k*256];
    s[threadIdx.x] = v;
    __syncthreads();
    for (int st = 128; st > 0; st >>= 1) {
        if (threadIdx.x < st) s[threadIdx.x] += s[threadIdx.x + st];
        __syncthreads();
    }
    if (threadIdx.x == 0) out[0] = s[0] / 2097152.0f;  // mean over 2*64*128*128
}

// ---------------- host ----------------
extern "C" void kernel_launch(void* const* d_in, const int* in_sizes, int n_in,
                              void* d_out, int out_size) {
    const float* fs    = (const float*)d_in[0];
    const float* ft    = (const float*)d_in[1];
    const float* w_q   = (const float*)d_in[2];
    const float* w_k   = (const float*)d_in[3];
    const float* w_v   = (const float*)d_in[4];
    const float* rel_h = (const float*)d_in[5];
    const float* rel_w = (const float*)d_in[6];
    const float* w1r   = (const float*)d_in[7];
    const float* w1i   = (const float*)d_in[8];
    const float* w0w   = (const float*)d_in[9];
    const float* w0b   = (const float*)d_in[10];
    const float* cvw   = (const float*)d_in[11];
    const float* cvb   = (const float*)d_in[12];
    const float* cv1w  = (const float*)d_in[13];
    const float* cv1b  = (const float*)d_in[14];
    const float* rate1 = (const float*)d_in[15];
    const float* rate2 = (const float*)d_in[16];

    static bool s_init = false;
    static cudaStream_t s2;
    static cudaEvent_t evFork, evJ;
    if (!s_init) {
        int loPri, hiPri;
        cudaDeviceGetStreamPriorityRange(&loPri, &hiPri);
        cudaStreamCreateWithPriority(&s2, cudaStreamNonBlocking, loPri);  // wsum = low priority
        cudaEventCreateWithFlags(&evFork, cudaEventDisableTiming);
        cudaEventCreateWithFlags(&evJ,    cudaEventDisableTiming);
        cudaFuncSetAttribute(qkv_kernel,     cudaFuncAttributeMaxDynamicSharedMemorySize, 49152);
        cudaFuncSetAttribute(attn_pf_kernel, cudaFuncAttributeMaxDynamicSharedMemorySize, 82432);
        s_init = true;
    }

    // ---- fork s2 from the capture stream ----
    cudaEventRecord(evFork, 0);
    cudaStreamWaitEvent(s2, evFork, 0);

    // ---- interleaved enqueue: wsum chunks (low-pri s2) with the chain (stream 0) ----
    precompute_M<<<1, 256>>>(w0w, w0b, cvw, cvb, cv1w, cv1b);              // 1
    qkv_kernel<<<dim3(128, 2, 3), 256, 49152>>>(fs, w_q, w_k, w_v);        // 2
    wsum_kernel<<<dim3(32, 16), 128, 0, s2>>>(w1r, w1i, 0);                // 3
    wsum_kernel<<<dim3(32, 16), 128, 0, s2>>>(w1r, w1i, 16);               // 4 (profiled)
    attn_pf_kernel<<<dim3(128, 2), 256, 82432>>>(rel_h, rel_w, ft, rate2); // 5 (+c32 row FFT)
    wsum_kernel<<<dim3(32, 16), 128, 0, s2>>>(w1r, w1i, 32);               // 6
    fwd_pass2<<<32, 256>>>();                                              // 7
    wsum_kernel<<<dim3(32, 16), 128, 0, s2>>>(w1r, w1i, 48);               // 8
    cudaEventRecord(evJ, s2);

    // ---- join + inverse FFT with fused freq-mul and loss ----
    cudaStreamWaitEvent(0, evJ, 0);
    invB_kernel<<<1024, 256>>>();                                          // 9
    inv_pass2_loss<<<2048, 256>>>(rate1);                                  // 10
    reduce_kernel<<<1, 256>>>((float*)d_out);                              // 11
}

// round 14
// speedup vs baseline: 1.2916x; 1.0914x over previous
#include <cuda_runtime.h>

// Problem constants
#define CC   64          // channels (CIN == COUT)
#define SS   128         // H == W
#define P    16384       // SS*SS pixels
#define NB   2           // batch

// ---------------- device scratch (static __device__, no allocations) ----------------
__device__ float  g_Q    [NB*CC*P];   // Q, later overwritten with t2 = r2*out2 - ft
__device__ float  g_Kc   [NB*CC*P];
__device__ float  g_Vc   [NB*CC*P];
__device__ float2 g_F    [NB*P];      // ortho fft2(out[:,32])
__device__ float2 g_bufA [NB*P];      // forward FFT ping buffer (c32 rows only)
__device__ float  g_wsumR[CC*P];
__device__ float  g_wsumI[CC*P];
__device__ float  g_M    [CC*CC];
__device__ float  g_bias [CC];
__device__ float  g_part [128];

// ---------------- warp FFT helpers ----------------
// AoS float2 row (stride 1)
__device__ __forceinline__ void fft128_row(float2* S, int lane, const float2* TW) {
    #pragma unroll
    for (int s = 1; s <= 7; s++) {
        int hf = 1 << (s - 1);
        __syncwarp();
        #pragma unroll
        for (int e = 0; e < 2; e++) {
            int bf = lane + 32*e;
            int j  = bf & (hf - 1);
            int i0 = ((bf >> (s - 1)) << s) + j;
            int i1 = i0 + hf;
            float2 w = TW[j << (7 - s)];
            float2 u = S[i0], v = S[i1];
            float tr = w.x*v.x - w.y*v.y;
            float ti = w.x*v.y + w.y*v.x;
            S[i0] = make_float2(u.x + tr, u.y + ti);
            S[i1] = make_float2(u.x - tr, u.y - ti);
        }
    }
    __syncwarp();
}

// SoA re/im with arbitrary stride (for fused 2D FFT)
__device__ __forceinline__ void fft128s(float* re, float* im, int lane, int stride,
                                        const float2* TW) {
    #pragma unroll
    for (int s = 1; s <= 7; s++) {
        int hf = 1 << (s - 1);
        __syncwarp();
        #pragma unroll
        for (int e = 0; e < 2; e++) {
            int bf = lane + 32*e;
            int j  = bf & (hf - 1);
            int i0 = ((bf >> (s - 1)) << s) + j;
            int i1 = i0 + hf;
            float2 w = TW[j << (7 - s)];
            int a0 = i0*stride, a1 = i1*stride;
            float ur = re[a0], ui = im[a0];
            float vr = re[a1], vi = im[a1];
            float tr = w.x*vr - w.y*vi;
            float ti = w.x*vi + w.y*vr;
            re[a0] = ur + tr; im[a0] = ui + ti;
            re[a1] = ur - tr; im[a1] = ui - ti;
        }
    }
    __syncwarp();
}

// ---------------- kernel: collapse conv chain to M, bias ----------------
__global__ void precompute_M(const float* __restrict__ w0,  const float* __restrict__ w0b,
                             const float* __restrict__ cv,  const float* __restrict__ cvb,
                             const float* __restrict__ cv1, const float* __restrict__ cv1b) {
    __shared__ float T[CC*CC];
    __shared__ float tb[CC];
    int tid = threadIdx.x;
    for (int idx = tid; idx < CC*CC; idx += 256) {
        int o = idx >> 6, c = idx & 63;
        float s = 0.f;
        #pragma unroll 8
        for (int k = 0; k < CC; k++) s += w0[o*CC + k] * cv[k*CC + c];
        T[idx] = s;
    }
    if (tid < CC) {
        float s = 0.f;
        for (int j = 0; j < CC; j++) s += w0[tid*CC + j] * cvb[j];
        tb[tid] = s + w0b[tid];
    }
    __syncthreads();
    for (int idx = tid; idx < CC*CC; idx += 256) {
        int o = idx >> 6, c = idx & 63;
        float s = 0.f;
        #pragma unroll 8
        for (int k = 0; k < CC; k++) s += cv1[o*CC + k] * T[k*CC + c];
        g_M[idx] = s;
    }
    if (tid < CC) {
        float s = 0.f;
        for (int k = 0; k < CC; k++) s += cv1[tid*CC + k] * tb[k];
        g_bias[tid] = s + cv1b[tid];
    }
}

// ---------------- kernel: Q/K/V 1x1 convs, one matrix per block (grid.z) ----------------
// grid (128 pixel-tiles, NB, 3), block 256, dyn smem 49152
__global__ void qkv_kernel(const float* __restrict__ fs,
                           const float* __restrict__ wq,
                           const float* __restrict__ wk,
                           const float* __restrict__ wv) {
    extern __shared__ float sm[];
    float* sw = sm;            // 64 * 64 (transposed: [k][o])
    float* sf = sm + 4096;     // 64 * 128
    int tid = threadIdx.x;
    int b   = blockIdx.y;
    int m   = blockIdx.z;
    int p0  = blockIdx.x * 128;

    const float* w = (m == 0) ? wq : ((m == 1) ? wk : wv);
    for (int idx = tid; idx < 4096; idx += 256) {
        int o = idx >> 6, k = idx & 63;
        sw[k*64 + o] = w[idx];
    }
    for (int idx = tid; idx < 8192; idx += 256) {
        int c = idx >> 7, pp = idx & 127;
        sf[c*128 + pp] = fs[((b*CC + c) << 14) + p0 + pp];
    }
    __syncthreads();

    int c0  = (tid >> 4) * 4;
    int pp0 = (tid & 15) * 8;

    float acc[4][8];
    #pragma unroll
    for (int i = 0; i < 4; i++)
        #pragma unroll
        for (int j = 0; j < 8; j++) acc[i][j] = 0.f;

    #pragma unroll 4
    for (int k = 0; k < 64; k++) {
        float4 w4 = *reinterpret_cast<const float4*>(&sw[k*64 + c0]);
        float4 fa = *reinterpret_cast<const float4*>(&sf[k*128 + pp0]);
        float4 fb = *reinterpret_cast<const float4*>(&sf[k*128 + pp0 + 4]);
        float wv4[4] = {w4.x, w4.y, w4.z, w4.w};
        float fv[8]  = {fa.x, fa.y, fa.z, fa.w, fb.x, fb.y, fb.z, fb.w};
        #pragma unroll
        for (int i = 0; i < 4; i++)
            #pragma unroll
            for (int j = 0; j < 8; j++)
                acc[i][j] += wv4[i] * fv[j];
    }
    float* dst = (m == 0) ? g_Q : ((m == 1) ? g_Kc : g_Vc);
    #pragma unroll
    for (int i = 0; i < 4; i++) {
        float* dp = dst + ((b*CC + c0 + i) << 14) + p0 + pp0;
        *reinterpret_cast<float4*>(dp)     = make_float4(acc[i][0], acc[i][1], acc[i][2], acc[i][3]);
        *reinterpret_cast<float4*>(dp + 4) = make_float4(acc[i][4], acc[i][5], acc[i][6], acc[i][7]);
    }
}

// ---------------- FUSED: attention + M@out GEMM + t2 epilogue + c32 row FFT ----------------
// grid (128 rows, NB), block 256, dyn smem 82432
__global__ void attn_pf_kernel(const float* __restrict__ relh,
                               const float* __restrict__ relw,
                               const float* __restrict__ ft,
                               const float* __restrict__ rate2) {
    extern __shared__ float sm[];
    float* sOut = sm;            // 64 * 128 = 8192
    float* sFt  = sm + 8192;     // 128 * 65 = 8320 (padded)
    float* sMT  = sm + 16512;    // 64 * 64  = 4096 (transposed [k][o])
    __shared__ float2 SF[128];   // c32 row FFT buffer
    __shared__ float2 TWF[64];   // forward twiddles
    int tid  = threadIdx.x;
    int wid  = tid >> 5;
    int lane = tid & 31;
    int h    = blockIdx.x;
    int b    = blockIdx.y;
    int p0   = h * 128;

    if (tid < 64) {
        float cs, sn;
        sincosf(-6.28318530717958647692f * (float)tid / 128.f, &cs, &sn);
        TWF[tid] = make_float2(cs, sn);
    }
    for (int idx = tid; idx < 8192; idx += 256) {
        int pp = idx >> 6, c = idx & 63;
        sFt[pp*65 + c] = ft[((long)(b*P + p0 + pp))*64 + c];
    }
    for (int idx = tid; idx < 4096; idx += 256) {
        int o = idx >> 6, k = idx & 63;
        sMT[k*64 + o] = g_M[idx];
    }

    int c0  = (tid >> 4) * 4;     // 4 channels per thread
    int pp0 = (tid & 15) * 8;     // 8 pixels per thread

    #pragma unroll
    for (int i = 0; i < 4; i++) {
        int c = c0 + i;
        bool rowbias = (c < 32);
        float b0, b1, b2;
        if (rowbias) { b0 = relh[c*3+0]; b1 = relh[c*3+1]; b2 = relh[c*3+2]; }
        else         { int cc = c - 32; b0 = relw[cc*3+0]; b1 = relw[cc*3+1]; b2 = relw[cc*3+2]; }

        float Ks[3][10], Vs[3][10];
        const float* Kb = g_Kc + ((b*CC + c) << 14);
        const float* Vb = g_Vc + ((b*CC + c) << 14);
        #pragma unroll
        for (int dh = 0; dh < 3; dh++) {
            int h2 = h - 1 + dh;
            if ((unsigned)h2 < 128u) {
                const float* kr = Kb + h2*128;
                const float* vr = Vb + h2*128;
                float4 ka = *reinterpret_cast<const float4*>(kr + pp0);
                float4 kc = *reinterpret_cast<const float4*>(kr + pp0 + 4);
                float4 va = *reinterpret_cast<const float4*>(vr + pp0);
                float4 vc = *reinterpret_cast<const float4*>(vr + pp0 + 4);
                Ks[dh][1]=ka.x; Ks[dh][2]=ka.y; Ks[dh][3]=ka.z; Ks[dh][4]=ka.w;
                Ks[dh][5]=kc.x; Ks[dh][6]=kc.y; Ks[dh][7]=kc.z; Ks[dh][8]=kc.w;
                Vs[dh][1]=va.x; Vs[dh][2]=va.y; Vs[dh][3]=va.z; Vs[dh][4]=va.w;
                Vs[dh][5]=vc.x; Vs[dh][6]=vc.y; Vs[dh][7]=vc.z; Vs[dh][8]=vc.w;
                Ks[dh][0] = (pp0 > 0)   ? kr[pp0-1] : 0.f;
                Ks[dh][9] = (pp0 < 120) ? kr[pp0+8] : 0.f;
                Vs[dh][0] = (pp0 > 0)   ? vr[pp0-1] : 0.f;
                Vs[dh][9] = (pp0 < 120) ? vr[pp0+8] : 0.f;
            } else {
                #pragma unroll
                for (int m2 = 0; m2 < 10; m2++) { Ks[dh][m2] = 0.f; Vs[dh][m2] = 0.f; }
            }
        }
        const float* qp = g_Q + ((b*CC + c) << 14) + p0 + pp0;
        float4 qa = *reinterpret_cast<const float4*>(qp);
        float4 qb = *reinterpret_cast<const float4*>(qp + 4);
        float q[8] = {qa.x, qa.y, qa.z, qa.w, qb.x, qb.y, qb.z, qb.w};

        float outv[8];
        #pragma unroll
        for (int j = 0; j < 8; j++) {
            float l[9], vv[9];
            float mx = -1e30f;
            #pragma unroll
            for (int dh = 0; dh < 3; dh++) {
                float bh = (dh == 0) ? b0 : ((dh == 1) ? b1 : b2);
                #pragma unroll
                for (int dw = 0; dw < 3; dw++) {
                    float bias = rowbias ? bh : ((dw == 0) ? b0 : ((dw == 1) ? b1 : b2));
                    int t = dh*3 + dw;
                    l[t]  = q[j] * (Ks[dh][j + dw] + bias);
                    vv[t] = Vs[dh][j + dw];
                    mx = fmaxf(mx, l[t]);
                }
            }
            float se = 0.f, acc = 0.f;
            #pragma unroll
            for (int t = 0; t < 9; t++) {
                float e = __expf(l[t] - mx);
                se  += e;
                acc += e * vv[t];
            }
            outv[j] = acc / se;
        }
        *reinterpret_cast<float4*>(&sOut[c*128 + pp0])     = make_float4(outv[0], outv[1], outv[2], outv[3]);
        *reinterpret_cast<float4*>(&sOut[c*128 + pp0 + 4]) = make_float4(outv[4], outv[5], outv[6], outv[7]);
    }
    __syncthreads();

    // ---- phase 2: GEMM out2 = M@out + bias; t2 = r2*out2 - ft ----
    float acc[4][8];
    #pragma unroll
    for (int i = 0; i < 4; i++) {
        float bb = g_bias[c0 + i];
        #pragma unroll
        for (int j = 0; j < 8; j++) acc[i][j] = bb;
    }
    #pragma unroll 4
    for (int k = 0; k < 64; k++) {
        float4 m4 = *reinterpret_cast<const float4*>(&sMT[k*64 + c0]);
        float4 fa = *reinterpret_cast<const float4*>(&sOut[k*128 + pp0]);
        float4 fb = *reinterpret_cast<const float4*>(&sOut[k*128 + pp0 + 4]);
        float mv[4] = {m4.x, m4.y, m4.z, m4.w};
        float fv[8] = {fa.x, fa.y, fa.z, fa.w, fb.x, fb.y, fb.z, fb.w};
        #pragma unroll
        for (int i = 0; i < 4; i++)
            #pragma unroll
            for (int j = 0; j < 8; j++)
                acc[i][j] += mv[i] * fv[j];
    }

    float r2 = rate2[0];
    #pragma unroll
    for (int i = 0; i < 4; i++) {
        int c = c0 + i;
        float o8[8];
        #pragma unroll
        for (int j = 0; j < 8; j++)
            o8[j] = r2 * acc[i][j] - sFt[(pp0 + j)*65 + c];
        float* dp = g_Q + ((b*CC + c) << 14) + p0 + pp0;
        *reinterpret_cast<float4*>(dp)     = make_float4(o8[0], o8[1], o8[2], o8[3]);
        *reinterpret_cast<float4*>(dp + 4) = make_float4(o8[4], o8[5], o8[6], o8[7]);
    }

    // ---- phase 3 (warp 0 only): forward row FFT of channel-32 row h -> g_bufA ----
    if (wid == 0) {
        #pragma unroll
        for (int e = 0; e < 4; e++) {
            int j = lane + e*32;
            int r = __brev((unsigned)j) >> 25;
            SF[r] = make_float2(sOut[32*128 + j], 0.f);
        }
        fft128_row(SF, lane, TWF);
        #pragma unroll
        for (int e = 0; e < 4; e++) {
            int j = lane + e*32;
            g_bufA[(long)b*P + j*128 + h] = SF[j];   // transposed store
        }
    }
}

// ---------------- forward column FFT (2 transforms) -> g_F ----------------
// grid 32 (= 2 transforms * 16 row-blocks), block 256
__global__ void fwd_pass2() {
    __shared__ float2 S[8][128];
    __shared__ float2 TW[64];
    int tid  = threadIdx.x;
    int t    = blockIdx.x >> 4;
    int rb   = blockIdx.x & 15;
    int wid  = tid >> 5;
    int lane = tid & 31;
    int a    = rb*8 + wid;

    if (tid < 64) {
        float cs, sn;
        sincosf(-6.28318530717958647692f * (float)tid / 128.f, &cs, &sn);
        TW[tid] = make_float2(cs, sn);
    }
    __syncthreads();

    const float2* p = g_bufA + (long)t*P + a*128;
    #pragma unroll
    for (int e = 0; e < 4; e++) {
        int j = lane + e*32;
        int r = __brev((unsigned)j) >> 25;
        S[wid][r] = p[j];
    }
    fft128_row(S[wid], lane, TW);
    __syncthreads();

    const float sc = 1.f/128.f;   // ortho fft2
    #pragma unroll
    for (int it = 0; it < 4; it++) {
        int el = it*256 + tid;
        int j  = el >> 3, aa = el & 7;
        float2 v = S[aa][j];
        g_F[(long)t*P + j*128 + rb*8 + aa] = make_float2(v.x*sc, v.y*sc);
    }
}

// ---------------- wsum chunk: 16 channels of the 512MB weights stream ----------------
// grid (32 rb, 16 ch), block 128; c = c0 + blockIdx.y
__global__ void __launch_bounds__(128) wsum_kernel(const float* __restrict__ w1r,
                                                   const float* __restrict__ w1i,
                                                   int c0) {
    int tid = threadIdx.x;
    int c   = c0 + blockIdx.y;
    int f4  = blockIdx.x * 128 + tid;   // float4 index in [0,4096)

    const float4* pR = reinterpret_cast<const float4*>(w1r + (size_t)c*CC*P) + f4;
    const float4* pI = reinterpret_cast<const float4*>(w1i + (size_t)c*CC*P) + f4;

    float4 aR = make_float4(0,0,0,0), aI = make_float4(0,0,0,0);
    #pragma unroll
    for (int g = 0; g < 8; g++) {
        float4 R[8], I[8];
        #pragma unroll
        for (int j = 0; j < 8; j++) R[j] = __ldcs(&pR[(g*8 + j)*4096]);
        #pragma unroll
        for (int j = 0; j < 8; j++) I[j] = __ldcs(&pI[(g*8 + j)*4096]);
        #pragma unroll
        for (int j = 0; j < 8; j++) {
            aR.x += R[j].x; aR.y += R[j].y; aR.z += R[j].z; aR.w += R[j].w;
            aI.x += I[j].x; aI.y += I[j].y; aI.z += I[j].z; aI.w += I[j].w;
        }
    }
    reinterpret_cast<float4*>(g_wsumR)[c*4096 + f4] = aR;
    reinterpret_cast<float4*>(g_wsumI)[c*4096 + f4] = aI;
}

// ---------------- FUSED: freq-mul + full 2D inverse FFT + loss ----------------
// grid (NB, 64 channels), block 512, dyn smem 132096 (SoA re/im, pitch 129)
__global__ void __launch_bounds__(512) inv2d_loss(const float* __restrict__ rate1) {
    extern __shared__ float sm[];
    float* Sre = sm;
    float* Sim = sm + 128*129;
    __shared__ float2 TW[64];
    __shared__ float red[512];
    int tid  = threadIdx.x;
    int wid  = tid >> 5;
    int lane = tid & 31;
    int b    = blockIdx.x;
    int c    = blockIdx.y;

    if (tid < 64) {
        float cs, sn;
        sincosf(6.28318530717958647692f * (float)tid / 128.f, &cs, &sn);
        TW[tid] = make_float2(cs, sn);
    }
    // load + freq multiply; bit-reverse v for the row pass
    const float2* Fp = g_F + b*P;
    const float*  wr = g_wsumR + c*P;
    const float*  wi = g_wsumI + c*P;
    for (int idx = tid; idx < 16384; idx += 512) {
        int u = idx >> 7, v = idx & 127;
        float2 F = Fp[idx];
        float sr = wr[idx], si = wi[idx];
        int vr_ = __brev((unsigned)v) >> 25;
        Sre[u*129 + vr_] = sr*F.x - si*F.y;
        Sim[u*129 + vr_] = sr*F.y + si*F.x;
    }
    __syncthreads();

    // row pass (along v): each of 16 warps handles 8 rows
    #pragma unroll
    for (int k = 0; k < 8; k++) {
        int r = wid*8 + k;
        fft128s(Sre + r*129, Sim + r*129, lane, 1, TW);
    }
    __syncthreads();

    // column pass (along u): bit-reverse column via registers, then strided FFT
    #pragma unroll
    for (int k = 0; k < 8; k++) {
        int v = wid*8 + k;
        float vr[4], vi[4];
        #pragma unroll
        for (int e = 0; e < 4; e++) {
            int j = lane + 32*e;
            vr[e] = Sre[j*129 + v];
            vi[e] = Sim[j*129 + v];
        }
        __syncwarp();
        #pragma unroll
        for (int e = 0; e < 4; e++) {
            int j  = lane + 32*e;
            int jr = __brev((unsigned)j) >> 25;
            Sre[jr*129 + v] = vr[e];
            Sim[jr*129 + v] = vi[e];
        }
        fft128s(Sre + v, Sim + v, lane, 129, TW);
    }
    __syncthreads();

    // loss: (r1/128 * Re + t2)^2 over the full 128x128 tile
    float r1s = rate1[0] * (1.f/128.f);
    const float* t2 = g_Q + ((long)(b*CC + c)) * P;
    float local = 0.f;
    for (int idx = tid; idx < 16384; idx += 512) {
        int h = idx >> 7, w = idx & 127;
        float val = r1s * Sre[h*129 + w] + t2[idx];
        local += val * val;
    }
    red[tid] = local;
    __syncthreads();
    for (int s = 256; s > 0; s >>= 1) {
        if (tid < s) red[tid] += red[tid + s];
        __syncthreads();
    }
    if (tid == 0) g_part[c*NB + b] = red[0];
}

__global__ void reduce_kernel(float* __restrict__ out) {
    __shared__ float s[128];
    s[threadIdx.x] = g_part[threadIdx.x];
    __syncthreads();
    for (int st = 64; st > 0; st >>= 1) {
        if (threadIdx.x < st) s[threadIdx.x] += s[threadIdx.x + st];
        __syncthreads();
    }
    if (threadIdx.x == 0) out[0] = s[0] / 2097152.0f;  // mean over 2*64*128*128
}

// ---------------- host ----------------
extern "C" void kernel_launch(void* const* d_in, const int* in_sizes, int n_in,
                              void* d_out, int out_size) {
    const float* fs    = (const float*)d_in[0];
    const float* ft    = (const float*)d_in[1];
    const float* w_q   = (const float*)d_in[2];
    const float* w_k   = (const float*)d_in[3];
    const float* w_v   = (const float*)d_in[4];
    const float* rel_h = (const float*)d_in[5];
    const float* rel_w = (const float*)d_in[6];
    const float* w1r   = (const float*)d_in[7];
    const float* w1i   = (const float*)d_in[8];
    const float* w0w   = (const float*)d_in[9];
    const float* w0b   = (const float*)d_in[10];
    const float* cvw   = (const float*)d_in[11];
    const float* cvb   = (const float*)d_in[12];
    const float* cv1w  = (const float*)d_in[13];
    const float* cv1b  = (const float*)d_in[14];
    const float* rate1 = (const float*)d_in[15];
    const float* rate2 = (const float*)d_in[16];

    static bool s_init = false;
    static cudaStream_t s2;
    static cudaEvent_t evFork, evJ;
    if (!s_init) {
        int loPri, hiPri;
        cudaDeviceGetStreamPriorityRange(&loPri, &hiPri);
        cudaStreamCreateWithPriority(&s2, cudaStreamNonBlocking, loPri);  // wsum = low priority
        cudaEventCreateWithFlags(&evFork, cudaEventDisableTiming);
        cudaEventCreateWithFlags(&evJ,    cudaEventDisableTiming);
        cudaFuncSetAttribute(qkv_kernel,     cudaFuncAttributeMaxDynamicSharedMemorySize, 49152);
        cudaFuncSetAttribute(attn_pf_kernel, cudaFuncAttributeMaxDynamicSharedMemorySize, 82432);
        cudaFuncSetAttribute(inv2d_loss,     cudaFuncAttributeMaxDynamicSharedMemorySize, 132096);
        s_init = true;
    }

    // ---- fork s2 from the capture stream ----
    cudaEventRecord(evFork, 0);
    cudaStreamWaitEvent(s2, evFork, 0);

    // ---- interleaved enqueue: wsum chunks (low-pri s2) with the chain (stream 0) ----
    precompute_M<<<1, 256>>>(w0w, w0b, cvw, cvb, cv1w, cv1b);              // 1
    qkv_kernel<<<dim3(128, 2, 3), 256, 49152>>>(fs, w_q, w_k, w_v);        // 2
    wsum_kernel<<<dim3(32, 16), 128, 0, s2>>>(w1r, w1i, 0);                // 3
    wsum_kernel<<<dim3(32, 16), 128, 0, s2>>>(w1r, w1i, 16);               // 4 (profiled)
    attn_pf_kernel<<<dim3(128, 2), 256, 82432>>>(rel_h, rel_w, ft, rate2); // 5 (+c32 row FFT)
    wsum_kernel<<<dim3(32, 16), 128, 0, s2>>>(w1r, w1i, 32);               // 6
    fwd_pass2<<<32, 256>>>();                                              // 7
    wsum_kernel<<<dim3(32, 16), 128, 0, s2>>>(w1r, w1i, 48);               // 8
    cudaEventRecord(evJ, s2);

    // ---- join + fused 2D inverse FFT + loss ----
    cudaStreamWaitEvent(0, evJ, 0);
    inv2d_loss<<<dim3(NB, CC), 512, 132096>>>(rate1);                      // 9
    reduce_kernel<<<1, 128>>>((float*)d_out);                              // 10
}